// round 14
// baseline (speedup 1.0000x reference)
#include <cuda_runtime.h>
#include <cuda_bf16.h>
#include <math.h>
#include <stdint.h>

#define DIMV   1024
#define HEADS  16
#define HD     64
#define BATCH  8
#define SEQ    1024
#define MTOT   (BATCH*SEQ)
#define SCALEF 0.125f

/* ------------------------------------------------------------------ */
/* scratch planes                                                      */
/* ------------------------------------------------------------------ */
#define PLANE (BATCH*HEADS*SEQ*HD)
__device__ __nv_bfloat16 g_qh[PLANE], g_ql[PLANE];
__device__ __nv_bfloat16 g_kh[PLANE], g_kl[PLANE];
__device__ __nv_bfloat16 g_vh[PLANE], g_vl[PLANE];
__device__ __nv_bfloat16 g_oh[(size_t)MTOT*DIMV], g_ol[(size_t)MTOT*DIMV];

__device__ __forceinline__ uint32_t smem_u32(const void* p) {
    uint32_t a;
    asm("{ .reg .u64 t; cvta.to.shared.u64 t, %1; cvt.u32.u64 %0, t; }"
        : "=r"(a) : "l"(p));
    return a;
}
__device__ __forceinline__ void ldm_x4(uint32_t* r, uint32_t addr) {
    asm volatile("ldmatrix.sync.aligned.m8n8.x4.shared.b16 {%0,%1,%2,%3}, [%4];"
                 : "=r"(r[0]), "=r"(r[1]), "=r"(r[2]), "=r"(r[3]) : "r"(addr));
}
__device__ __forceinline__ void ldm_x4_t(uint32_t* r, uint32_t addr) {
    asm volatile("ldmatrix.sync.aligned.m8n8.x4.trans.shared.b16 {%0,%1,%2,%3}, [%4];"
                 : "=r"(r[0]), "=r"(r[1]), "=r"(r[2]), "=r"(r[3]) : "r"(addr));
}
__device__ __forceinline__ void mma_bf16(float* c, const uint32_t* a, const uint32_t* b) {
    asm volatile("mma.sync.aligned.m16n8k16.row.col.f32.bf16.bf16.f32 "
                 "{%0,%1,%2,%3}, {%4,%5,%6,%7}, {%8,%9}, {%0,%1,%2,%3};"
                 : "+f"(c[0]), "+f"(c[1]), "+f"(c[2]), "+f"(c[3])
                 : "r"(a[0]), "r"(a[1]), "r"(a[2]), "r"(a[3]), "r"(b[0]), "r"(b[1]));
}
__device__ __forceinline__ void cpa16(uint32_t sm, const void* gm) {
    asm volatile("cp.async.ca.shared.global [%0], [%1], 16;" :: "r"(sm), "l"(gm));
}
#define CP_COMMIT() asm volatile("cp.async.commit_group;" ::: "memory")
#define CP_WAIT0()  asm volatile("cp.async.wait_group 0;" ::: "memory")

/* ------------------------------------------------------------------ */
/* GEMM BK=64 (round-13 proven): 128x128 tile, 8 warps 2x4, 2 CTA/SM.  */
/* ------------------------------------------------------------------ */
#define SPK   72
#define PL_E  (128*SPK)
#define GS_B  (4*PL_E*2)

__global__ void __launch_bounds__(256, 2) gemm_qkv(
    const float* __restrict__ Ap, const float* __restrict__ Bw)
{
    extern __shared__ __nv_bfloat16 smg[];
    const uint32_t s0 = smem_u32(smg);
    const uint32_t uAh = s0;
    const uint32_t uAl = s0 + PL_E * 2;
    const uint32_t uBh = s0 + 2 * PL_E * 2;
    const uint32_t uBl = s0 + 3 * PL_E * 2;

    const int tid  = threadIdx.x;
    const int lane = tid & 31;
    const int wid  = tid >> 5;
    const int wm   = wid >> 2;
    const int wn   = wid & 3;
    const int m0   = blockIdx.y * 128;
    const int n0   = blockIdx.x * 128;

    const int a_lrow = (lane & 7) + ((lane >> 3) & 1) * 8;
    const int a_lkof = (lane >> 4) * 8;
    const int b_lrow = (lane & 7) + (lane >> 4) * 8;
    const int b_lkof = ((lane >> 3) & 1) * 8;

    float acc[4][4][4];
#pragma unroll
    for (int i = 0; i < 4; i++)
#pragma unroll
        for (int j = 0; j < 4; j++)
#pragma unroll
            for (int r = 0; r < 4; r++) acc[i][j][r] = 0.f;

    for (int k0 = 0; k0 < DIMV; k0 += 64) {
#pragma unroll
        for (int j = 0; j < 8; j++) {
            int v   = tid + j * 256;
            int row = v >> 4;
            int q   = v & 15;
            uint32_t so = (uint32_t)(row * SPK + q * 4) * 2;

            float4 a = *(const float4*)&Ap[(size_t)(m0 + row) * DIMV + k0 + q * 4];
            __nv_bfloat162 h01 = __floats2bfloat162_rn(a.x, a.y);
            __nv_bfloat162 h23 = __floats2bfloat162_rn(a.z, a.w);
            __nv_bfloat162 l01 = __floats2bfloat162_rn(a.x - __bfloat162float(h01.x),
                                                       a.y - __bfloat162float(h01.y));
            __nv_bfloat162 l23 = __floats2bfloat162_rn(a.z - __bfloat162float(h23.x),
                                                       a.w - __bfloat162float(h23.y));
            asm volatile("st.shared.v2.u32 [%0], {%1,%2};" ::
                "r"(uAh + so), "r"(*(uint32_t*)&h01), "r"(*(uint32_t*)&h23));
            asm volatile("st.shared.v2.u32 [%0], {%1,%2};" ::
                "r"(uAl + so), "r"(*(uint32_t*)&l01), "r"(*(uint32_t*)&l23));

            float4 b = *(const float4*)&Bw[(size_t)(n0 + row) * DIMV + k0 + q * 4];
            __nv_bfloat162 bh01 = __floats2bfloat162_rn(b.x, b.y);
            __nv_bfloat162 bh23 = __floats2bfloat162_rn(b.z, b.w);
            __nv_bfloat162 bl01 = __floats2bfloat162_rn(b.x - __bfloat162float(bh01.x),
                                                        b.y - __bfloat162float(bh01.y));
            __nv_bfloat162 bl23 = __floats2bfloat162_rn(b.z - __bfloat162float(bh23.x),
                                                        b.w - __bfloat162float(bh23.y));
            asm volatile("st.shared.v2.u32 [%0], {%1,%2};" ::
                "r"(uBh + so), "r"(*(uint32_t*)&bh01), "r"(*(uint32_t*)&bh23));
            asm volatile("st.shared.v2.u32 [%0], {%1,%2};" ::
                "r"(uBl + so), "r"(*(uint32_t*)&bl01), "r"(*(uint32_t*)&bl23));
        }
        __syncthreads();

#pragma unroll
        for (int ks = 0; ks < 4; ks++) {
            const int kk = ks * 16;
            uint32_t bfh[2][4], bfl[2][4];
#pragma unroll
            for (int bi = 0; bi < 2; bi++) {
                uint32_t boff = (uint32_t)((wn * 32 + bi * 16 + b_lrow) * SPK
                                           + kk + b_lkof) * 2;
                ldm_x4(bfh[bi], uBh + boff);
                ldm_x4(bfl[bi], uBl + boff);
            }
#pragma unroll
            for (int mi = 0; mi < 4; mi++) {
                uint32_t af_h[4], af_l[4];
                uint32_t aoff = (uint32_t)((wm * 64 + mi * 16 + a_lrow) * SPK
                                           + kk + a_lkof) * 2;
                ldm_x4(af_h, uAh + aoff);
                ldm_x4(af_l, uAl + aoff);
#pragma unroll
                for (int ni = 0; ni < 4; ni++) {
                    const uint32_t* bh = &bfh[ni >> 1][(ni & 1) * 2];
                    const uint32_t* bl = &bfl[ni >> 1][(ni & 1) * 2];
                    mma_bf16(acc[mi][ni], af_h, bh);
                    mma_bf16(acc[mi][ni], af_h, bl);
                    mma_bf16(acc[mi][ni], af_l, bh);
                }
            }
        }
        __syncthreads();
    }

    const int r_base = wm * 64 + (lane >> 2);
    const int c_base = wn * 32 + (lane & 3) * 2;
#pragma unroll
    for (int mi = 0; mi < 4; mi++) {
#pragma unroll
        for (int ni = 0; ni < 4; ni++) {
            int gcol = n0 + c_base + ni * 8;
#pragma unroll
            for (int half = 0; half < 2; half++) {
                int grow = m0 + r_base + mi * 16 + half * 8;
                float v0 = acc[mi][ni][half * 2 + 0];
                float v1 = acc[mi][ni][half * 2 + 1];
                int qkv = gcol >> 10;
                int hh  = (gcol >> 6) & 15;
                int dd  = gcol & 63;
                int b   = grow >> 10;
                int sp  = grow & 1023;
                size_t off = (((size_t)(b * HEADS + hh) * SEQ) + sp) * HD + dd;
                if (qkv == 0) { v0 *= SCALEF; v1 *= SCALEF; }
                __nv_bfloat16 h0 = __float2bfloat16_rn(v0);
                __nv_bfloat16 h1 = __float2bfloat16_rn(v1);
                __nv_bfloat16 l0 = __float2bfloat16_rn(v0 - __bfloat162float(h0));
                __nv_bfloat16 l1 = __float2bfloat16_rn(v1 - __bfloat162float(h1));
                __nv_bfloat16* ph = (qkv == 0) ? g_qh : (qkv == 1) ? g_kh : g_vh;
                __nv_bfloat16* pl = (qkv == 0) ? g_ql : (qkv == 1) ? g_kl : g_vl;
                *(__nv_bfloat162*)&ph[off] = __halves2bfloat162(h0, h1);
                *(__nv_bfloat162*)&pl[off] = __halves2bfloat162(l0, l1);
            }
        }
    }
}

__global__ void __launch_bounds__(256, 2) gemm_proj(
    const float* __restrict__ Bw, const float* __restrict__ bias,
    float* __restrict__ out)
{
    extern __shared__ __nv_bfloat16 smg[];
    const uint32_t s0 = smem_u32(smg);
    const uint32_t uAh = s0;
    const uint32_t uAl = s0 + PL_E * 2;
    const uint32_t uBh = s0 + 2 * PL_E * 2;
    const uint32_t uBl = s0 + 3 * PL_E * 2;

    const int tid  = threadIdx.x;
    const int lane = tid & 31;
    const int wid  = tid >> 5;
    const int wm   = wid >> 2;
    const int wn   = wid & 3;
    const int m0   = blockIdx.y * 128;
    const int n0   = blockIdx.x * 128;

    const int a_lrow = (lane & 7) + ((lane >> 3) & 1) * 8;
    const int a_lkof = (lane >> 4) * 8;
    const int b_lrow = (lane & 7) + (lane >> 4) * 8;
    const int b_lkof = ((lane >> 3) & 1) * 8;

    float acc[4][4][4];
#pragma unroll
    for (int i = 0; i < 4; i++)
#pragma unroll
        for (int j = 0; j < 4; j++)
#pragma unroll
            for (int r = 0; r < 4; r++) acc[i][j][r] = 0.f;

    for (int k0 = 0; k0 < DIMV; k0 += 64) {
#pragma unroll
        for (int j = 0; j < 4; j++) {
            int v   = tid + j * 256;
            int row = v >> 3;
            int c8  = (v & 7) * 8;
            uint32_t so = (uint32_t)(row * SPK + c8) * 2;
            size_t go = (size_t)(m0 + row) * DIMV + k0 + c8;
            uint4 ah = *(const uint4*)&g_oh[go];
            uint4 al = *(const uint4*)&g_ol[go];
            asm volatile("st.shared.v4.b32 [%0], {%1,%2,%3,%4};" ::
                "r"(uAh + so), "r"(ah.x), "r"(ah.y), "r"(ah.z), "r"(ah.w));
            asm volatile("st.shared.v4.b32 [%0], {%1,%2,%3,%4};" ::
                "r"(uAl + so), "r"(al.x), "r"(al.y), "r"(al.z), "r"(al.w));
        }
#pragma unroll
        for (int j = 0; j < 8; j++) {
            int v   = tid + j * 256;
            int row = v >> 4;
            int q   = v & 15;
            uint32_t so = (uint32_t)(row * SPK + q * 4) * 2;
            float4 b = *(const float4*)&Bw[(size_t)(n0 + row) * DIMV + k0 + q * 4];
            __nv_bfloat162 bh01 = __floats2bfloat162_rn(b.x, b.y);
            __nv_bfloat162 bh23 = __floats2bfloat162_rn(b.z, b.w);
            __nv_bfloat162 bl01 = __floats2bfloat162_rn(b.x - __bfloat162float(bh01.x),
                                                        b.y - __bfloat162float(bh01.y));
            __nv_bfloat162 bl23 = __floats2bfloat162_rn(b.z - __bfloat162float(bh23.x),
                                                        b.w - __bfloat162float(bh23.y));
            asm volatile("st.shared.v2.u32 [%0], {%1,%2};" ::
                "r"(uBh + so), "r"(*(uint32_t*)&bh01), "r"(*(uint32_t*)&bh23));
            asm volatile("st.shared.v2.u32 [%0], {%1,%2};" ::
                "r"(uBl + so), "r"(*(uint32_t*)&bl01), "r"(*(uint32_t*)&bl23));
        }
        __syncthreads();

#pragma unroll
        for (int ks = 0; ks < 4; ks++) {
            const int kk = ks * 16;
            uint32_t bfh[2][4], bfl[2][4];
#pragma unroll
            for (int bi = 0; bi < 2; bi++) {
                uint32_t boff = (uint32_t)((wn * 32 + bi * 16 + b_lrow) * SPK
                                           + kk + b_lkof) * 2;
                ldm_x4(bfh[bi], uBh + boff);
                ldm_x4(bfl[bi], uBl + boff);
            }
#pragma unroll
            for (int mi = 0; mi < 4; mi++) {
                uint32_t af_h[4], af_l[4];
                uint32_t aoff = (uint32_t)((wm * 64 + mi * 16 + a_lrow) * SPK
                                           + kk + a_lkof) * 2;
                ldm_x4(af_h, uAh + aoff);
                ldm_x4(af_l, uAl + aoff);
#pragma unroll
                for (int ni = 0; ni < 4; ni++) {
                    const uint32_t* bh = &bfh[ni >> 1][(ni & 1) * 2];
                    const uint32_t* bl = &bfl[ni >> 1][(ni & 1) * 2];
                    mma_bf16(acc[mi][ni], af_h, bh);
                    mma_bf16(acc[mi][ni], af_h, bl);
                    mma_bf16(acc[mi][ni], af_l, bh);
                }
            }
        }
        __syncthreads();
    }

    const int r_base = wm * 64 + (lane >> 2);
    const int c_base = wn * 32 + (lane & 3) * 2;
#pragma unroll
    for (int mi = 0; mi < 4; mi++) {
#pragma unroll
        for (int ni = 0; ni < 4; ni++) {
            int gcol = n0 + c_base + ni * 8;
#pragma unroll
            for (int half = 0; half < 2; half++) {
                int grow = m0 + r_base + mi * 16 + half * 8;
                float2 bb = *(const float2*)&bias[gcol];
                *(float2*)&out[(size_t)grow * DIMV + gcol] =
                    make_float2(acc[mi][ni][half * 2 + 0] + bb.x,
                                acc[mi][ni][half * 2 + 1] + bb.y);
            }
        }
    }
}

/* ------------------------------------------------------------------ */
/* Attention: double-buffered K/V via cp.async, 1 sync per chunk.      */
/* ------------------------------------------------------------------ */
#define QP 72
#define KV_PL (64*QP)
#define KVBUF (4*KV_PL)
#define ASMEM ((2*128*QP + 2*KVBUF) * 2)   /* 110592 B */

__global__ void __launch_bounds__(256) attn_mma()
{
    extern __shared__ __nv_bfloat16 smb[];
    const uint32_t s0  = smem_u32(smb);
    const uint32_t uQh = s0;
    const uint32_t uQl = s0 + (uint32_t)(128 * QP) * 2;
    const uint32_t uKV = s0 + (uint32_t)(2 * 128 * QP) * 2;

    const int tid  = threadIdx.x;
    const int lane = tid & 31;
    const int wid  = tid >> 5;
    const int bh   = blockIdx.y;
    const int m0   = blockIdx.x * 128;

    const size_t pbase = (size_t)bh * SEQ * HD;
    const __nv_bfloat16* pqh = g_qh + pbase;
    const __nv_bfloat16* pql = g_ql + pbase;
    const __nv_bfloat16* pkh = g_kh + pbase;
    const __nv_bfloat16* pkl = g_kl + pbase;
    const __nv_bfloat16* pvh = g_vh + pbase;
    const __nv_bfloat16* pvl = g_vl + pbase;

    /* K/V chunk loader: cp.async 16B x8 per thread into buffer buf */
    auto kv_load = [&](int c, int buf) {
        const int key0 = c * 64;
        const int row  = tid >> 2;              /* 0..63 */
        const int col  = (tid & 3) * 16;        /* bf16 elem */
        const uint32_t sb = uKV + (uint32_t)buf * (KVBUF * 2)
                          + (uint32_t)(row * QP + col) * 2;
        const size_t go = (size_t)(key0 + row) * HD + col;
        cpa16(sb + 0*KV_PL*2,      &pkh[go]);
        cpa16(sb + 0*KV_PL*2 + 16, &pkh[go + 8]);
        cpa16(sb + 1*KV_PL*2,      &pkl[go]);
        cpa16(sb + 1*KV_PL*2 + 16, &pkl[go + 8]);
        cpa16(sb + 2*KV_PL*2,      &pvh[go]);
        cpa16(sb + 2*KV_PL*2 + 16, &pvh[go + 8]);
        cpa16(sb + 3*KV_PL*2,      &pvl[go]);
        cpa16(sb + 3*KV_PL*2 + 16, &pvl[go + 8]);
    };

    /* Q tile load (regular stores) */
#pragma unroll
    for (int t = 0; t < 8; t++) {
        int idx = t * 256 + tid;
        int row = idx >> 4;
        int g   = idx & 15;
        size_t go = (size_t)(m0 + row) * HD + g * 4;
        uint2 vh = *(const uint2*)&pqh[go];
        uint2 vl = *(const uint2*)&pql[go];
        asm volatile("st.shared.v2.u32 [%0], {%1,%2};" ::
            "r"(uQh + (uint32_t)(row * QP + g * 4) * 2), "r"(vh.x), "r"(vh.y));
        asm volatile("st.shared.v2.u32 [%0], {%1,%2};" ::
            "r"(uQl + (uint32_t)(row * QP + g * 4) * 2), "r"(vl.x), "r"(vl.y));
    }

    /* preload chunk 0 */
    kv_load(0, 0);
    CP_COMMIT();

    float o[8][4];
#pragma unroll
    for (int n = 0; n < 8; n++)
#pragma unroll
        for (int r = 0; r < 4; r++) o[n][r] = 0.f;
    float mrow[2] = {-1e30f, -1e30f};
    float lrow[2] = {0.f, 0.f};

    const int a_row = wid * 16 + (lane & 15);
    const int a_kof = (lane >> 4) * 8;
    const int b_row = (lane & 7) + (lane >> 4) * 8;
    const int b_kof = ((lane >> 3) & 1) * 8;
    const int v_key = ((lane >> 3) & 1) * 8 + (lane & 7);
    const int v_col = (lane >> 4) * 8;

    CP_WAIT0();
    __syncthreads();

    for (int c = 0; c < 16; c++) {
        /* issue prefetch of next chunk into other buffer */
        if (c + 1 < 16) {
            kv_load(c + 1, (c + 1) & 1);
            CP_COMMIT();
        }

        const uint32_t bb  = uKV + (uint32_t)(c & 1) * (KVBUF * 2);
        const uint32_t uKh = bb;
        const uint32_t uKl = bb + KV_PL * 2;
        const uint32_t uVh = bb + 2 * KV_PL * 2;
        const uint32_t uVl = bb + 3 * KV_PL * 2;

        float s[8][4];
#pragma unroll
        for (int n = 0; n < 8; n++)
#pragma unroll
            for (int r = 0; r < 4; r++) s[n][r] = 0.f;

#pragma unroll
        for (int kk = 0; kk < 4; kk++) {
            uint32_t qhf[4], qlf[4];
            uint32_t aoff = (uint32_t)(a_row * QP + kk * 16 + a_kof) * 2;
            ldm_x4(qhf, uQh + aoff);
            ldm_x4(qlf, uQl + aoff);

            uint32_t kbh[4][4], kbl[4][4];
#pragma unroll
            for (int bi = 0; bi < 4; bi++) {
                uint32_t boff = (uint32_t)((bi * 16 + b_row) * QP + kk * 16 + b_kof) * 2;
                ldm_x4(kbh[bi], uKh + boff);
                ldm_x4(kbl[bi], uKl + boff);
            }
#pragma unroll
            for (int ni = 0; ni < 8; ni++)
                mma_bf16(s[ni], qhf, &kbh[ni >> 1][(ni & 1) * 2]);
#pragma unroll
            for (int ni = 0; ni < 8; ni++)
                mma_bf16(s[ni], qhf, &kbl[ni >> 1][(ni & 1) * 2]);
#pragma unroll
            for (int ni = 0; ni < 8; ni++)
                mma_bf16(s[ni], qlf, &kbh[ni >> 1][(ni & 1) * 2]);
        }

        float alpha[2];
#pragma unroll
        for (int r = 0; r < 2; r++) {
            float mx = -1e30f;
#pragma unroll
            for (int ni = 0; ni < 8; ni++)
                mx = fmaxf(mx, fmaxf(s[ni][r * 2], s[ni][r * 2 + 1]));
            mx = fmaxf(mx, __shfl_xor_sync(0xffffffffu, mx, 1));
            mx = fmaxf(mx, __shfl_xor_sync(0xffffffffu, mx, 2));
            float mnew = fmaxf(mrow[r], mx);
            alpha[r] = __expf(mrow[r] - mnew);
            mrow[r] = mnew;
            float ls = 0.f;
#pragma unroll
            for (int ni = 0; ni < 8; ni++) {
                s[ni][r * 2]     = __expf(s[ni][r * 2]     - mnew);
                s[ni][r * 2 + 1] = __expf(s[ni][r * 2 + 1] - mnew);
                ls += s[ni][r * 2] + s[ni][r * 2 + 1];
            }
            ls += __shfl_xor_sync(0xffffffffu, ls, 1);
            ls += __shfl_xor_sync(0xffffffffu, ls, 2);
            lrow[r] = lrow[r] * alpha[r] + ls;
#pragma unroll
            for (int ni = 0; ni < 8; ni++) {
                o[ni][r * 2]     *= alpha[r];
                o[ni][r * 2 + 1] *= alpha[r];
            }
        }

#pragma unroll
        for (int kk = 0; kk < 4; kk++) {
            uint32_t pha[4], pla[4];
#pragma unroll
            for (int q = 0; q < 4; q++) {
                float f0 = (q & 2) ? s[2 * kk + 1][(q & 1) * 2]     : s[2 * kk][(q & 1) * 2];
                float f1 = (q & 2) ? s[2 * kk + 1][(q & 1) * 2 + 1] : s[2 * kk][(q & 1) * 2 + 1];
                __nv_bfloat162 h2 = __floats2bfloat162_rn(f0, f1);
                __nv_bfloat162 l2 = __floats2bfloat162_rn(f0 - __bfloat162float(h2.x),
                                                          f1 - __bfloat162float(h2.y));
                pha[q] = *(uint32_t*)&h2;
                pla[q] = *(uint32_t*)&l2;
            }
            uint32_t vbh[4][4], vbl[4][4];
#pragma unroll
            for (int np = 0; np < 4; np++) {
                uint32_t voff = (uint32_t)((kk * 16 + v_key) * QP + np * 16 + v_col) * 2;
                ldm_x4_t(vbh[np], uVh + voff);
                ldm_x4_t(vbl[np], uVl + voff);
            }
#pragma unroll
            for (int ni = 0; ni < 8; ni++)
                mma_bf16(o[ni], pha, &vbh[ni >> 1][(ni & 1) * 2]);
#pragma unroll
            for (int ni = 0; ni < 8; ni++)
                mma_bf16(o[ni], pha, &vbl[ni >> 1][(ni & 1) * 2]);
#pragma unroll
            for (int ni = 0; ni < 8; ni++)
                mma_bf16(o[ni], pla, &vbh[ni >> 1][(ni & 1) * 2]);
        }

        if (c + 1 < 16) {
            CP_WAIT0();
            __syncthreads();
        }
    }

    const int b = bh >> 4;
    const int h = bh & 15;
#pragma unroll
    for (int r = 0; r < 2; r++) {
        float inv = 1.f / lrow[r];
        int row = m0 + wid * 16 + (lane >> 2) + r * 8;
        size_t base = ((size_t)(b * SEQ + row)) * DIMV + h * HD + (lane & 3) * 2;
#pragma unroll
        for (int ni = 0; ni < 8; ni++) {
            float f0 = o[ni][r * 2] * inv;
            float f1 = o[ni][r * 2 + 1] * inv;
            __nv_bfloat162 h2 = __floats2bfloat162_rn(f0, f1);
            __nv_bfloat162 l2 = __floats2bfloat162_rn(f0 - __bfloat162float(h2.x),
                                                      f1 - __bfloat162float(h2.y));
            *(__nv_bfloat162*)&g_oh[base + ni * 8] = h2;
            *(__nv_bfloat162*)&g_ol[base + ni * 8] = l2;
        }
    }
}

/* ------------------------------------------------------------------ */
extern "C" void kernel_launch(void* const* d_in, const int* in_sizes, int n_in,
                              void* d_out, int out_size)
{
    const float* x = nullptr;
    const float* Wqkv = nullptr;
    const float* Wproj = nullptr;
    const float* bproj = nullptr;
    for (int i = 0; i < n_in; i++) {
        switch (in_sizes[i]) {
            case 8388608: x     = (const float*)d_in[i]; break;
            case 3145728: Wqkv  = (const float*)d_in[i]; break;
            case 1048576: Wproj = (const float*)d_in[i]; break;
            case 1024:    bproj = (const float*)d_in[i]; break;
            default: break;
        }
    }
    float* out = (float*)d_out;

    /* QKV GEMM (BK=64, 2 CTA/SM) */
    {
        cudaFuncSetAttribute(gemm_qkv, cudaFuncAttributeMaxDynamicSharedMemorySize,
                             GS_B);
        dim3 grid(3 * DIMV / 128, MTOT / 128);
        gemm_qkv<<<grid, 256, GS_B>>>(x, Wqkv);
    }

    /* attention (cp.async double-buffered K/V) -> o planes */
    {
        cudaFuncSetAttribute(attn_mma, cudaFuncAttributeMaxDynamicSharedMemorySize,
                             ASMEM);
        dim3 grid(SEQ / 128, BATCH * HEADS);
        attn_mma<<<grid, 256, ASMEM>>>();
    }

    /* projection GEMM (BK=64) + bias */
    {
        cudaFuncSetAttribute(gemm_proj, cudaFuncAttributeMaxDynamicSharedMemorySize,
                             GS_B);
        dim3 grid(DIMV / 128, MTOT / 128);
        gemm_proj<<<grid, 256, GS_B>>>(Wproj, bproj, out);
    }
    (void)out_size; (void)n_in;
}

// round 15
// speedup vs baseline: 1.1310x; 1.1310x over previous
#include <cuda_runtime.h>
#include <cuda_bf16.h>
#include <cuda_fp16.h>
#include <math.h>
#include <stdint.h>

#define DIMV   1024
#define HEADS  16
#define HD     64
#define BATCH  8
#define SEQ    1024
#define MTOT   (BATCH*SEQ)
#define SCALEF 0.125f

/* ------------------------------------------------------------------ */
/* scratch planes: q,k bf16 hi/lo; v fp16 hi/lo; o fp16 single         */
/* ------------------------------------------------------------------ */
#define PLANE (BATCH*HEADS*SEQ*HD)
__device__ __nv_bfloat16 g_qh[PLANE], g_ql[PLANE];
__device__ __nv_bfloat16 g_kh[PLANE], g_kl[PLANE];
__device__ __half        g_vh[PLANE], g_vl[PLANE];
__device__ __half        g_o [(size_t)MTOT*DIMV];

__device__ __forceinline__ uint32_t smem_u32(const void* p) {
    uint32_t a;
    asm("{ .reg .u64 t; cvta.to.shared.u64 t, %1; cvt.u32.u64 %0, t; }"
        : "=r"(a) : "l"(p));
    return a;
}
__device__ __forceinline__ void ldm_x4(uint32_t* r, uint32_t addr) {
    asm volatile("ldmatrix.sync.aligned.m8n8.x4.shared.b16 {%0,%1,%2,%3}, [%4];"
                 : "=r"(r[0]), "=r"(r[1]), "=r"(r[2]), "=r"(r[3]) : "r"(addr));
}
__device__ __forceinline__ void ldm_x4_t(uint32_t* r, uint32_t addr) {
    asm volatile("ldmatrix.sync.aligned.m8n8.x4.trans.shared.b16 {%0,%1,%2,%3}, [%4];"
                 : "=r"(r[0]), "=r"(r[1]), "=r"(r[2]), "=r"(r[3]) : "r"(addr));
}
__device__ __forceinline__ void mma_bf16(float* c, const uint32_t* a, const uint32_t* b) {
    asm volatile("mma.sync.aligned.m16n8k16.row.col.f32.bf16.bf16.f32 "
                 "{%0,%1,%2,%3}, {%4,%5,%6,%7}, {%8,%9}, {%0,%1,%2,%3};"
                 : "+f"(c[0]), "+f"(c[1]), "+f"(c[2]), "+f"(c[3])
                 : "r"(a[0]), "r"(a[1]), "r"(a[2]), "r"(a[3]), "r"(b[0]), "r"(b[1]));
}
__device__ __forceinline__ void mma_fp16(float* c, const uint32_t* a, const uint32_t* b) {
    asm volatile("mma.sync.aligned.m16n8k16.row.col.f32.f16.f16.f32 "
                 "{%0,%1,%2,%3}, {%4,%5,%6,%7}, {%8,%9}, {%0,%1,%2,%3};"
                 : "+f"(c[0]), "+f"(c[1]), "+f"(c[2]), "+f"(c[3])
                 : "r"(a[0]), "r"(a[1]), "r"(a[2]), "r"(a[3]), "r"(b[0]), "r"(b[1]));
}

/* ------------------------------------------------------------------ */
/* QKV GEMM (round-13 proven): BK=64, 128x128, 8 warps 2x4, 2 CTA/SM. */
/* Epilogue: q,k -> bf16 hi/lo planes (Q scaled); v -> fp16 hi/lo.    */
/* ------------------------------------------------------------------ */
#define SPK   72
#define PL_E  (128*SPK)
#define GS_B  (4*PL_E*2)

__global__ void __launch_bounds__(256, 2) gemm_qkv(
    const float* __restrict__ Ap, const float* __restrict__ Bw)
{
    extern __shared__ __nv_bfloat16 smg[];
    const uint32_t s0 = smem_u32(smg);
    const uint32_t uAh = s0;
    const uint32_t uAl = s0 + PL_E * 2;
    const uint32_t uBh = s0 + 2 * PL_E * 2;
    const uint32_t uBl = s0 + 3 * PL_E * 2;

    const int tid  = threadIdx.x;
    const int lane = tid & 31;
    const int wid  = tid >> 5;
    const int wm   = wid >> 2;
    const int wn   = wid & 3;
    const int m0   = blockIdx.y * 128;
    const int n0   = blockIdx.x * 128;

    const int a_lrow = (lane & 7) + ((lane >> 3) & 1) * 8;
    const int a_lkof = (lane >> 4) * 8;
    const int b_lrow = (lane & 7) + (lane >> 4) * 8;
    const int b_lkof = ((lane >> 3) & 1) * 8;

    float acc[4][4][4];
#pragma unroll
    for (int i = 0; i < 4; i++)
#pragma unroll
        for (int j = 0; j < 4; j++)
#pragma unroll
            for (int r = 0; r < 4; r++) acc[i][j][r] = 0.f;

    for (int k0 = 0; k0 < DIMV; k0 += 64) {
#pragma unroll
        for (int j = 0; j < 8; j++) {
            int v   = tid + j * 256;
            int row = v >> 4;
            int q   = v & 15;
            uint32_t so = (uint32_t)(row * SPK + q * 4) * 2;

            float4 a = *(const float4*)&Ap[(size_t)(m0 + row) * DIMV + k0 + q * 4];
            __nv_bfloat162 h01 = __floats2bfloat162_rn(a.x, a.y);
            __nv_bfloat162 h23 = __floats2bfloat162_rn(a.z, a.w);
            __nv_bfloat162 l01 = __floats2bfloat162_rn(a.x - __bfloat162float(h01.x),
                                                       a.y - __bfloat162float(h01.y));
            __nv_bfloat162 l23 = __floats2bfloat162_rn(a.z - __bfloat162float(h23.x),
                                                       a.w - __bfloat162float(h23.y));
            asm volatile("st.shared.v2.u32 [%0], {%1,%2};" ::
                "r"(uAh + so), "r"(*(uint32_t*)&h01), "r"(*(uint32_t*)&h23));
            asm volatile("st.shared.v2.u32 [%0], {%1,%2};" ::
                "r"(uAl + so), "r"(*(uint32_t*)&l01), "r"(*(uint32_t*)&l23));

            float4 b = *(const float4*)&Bw[(size_t)(n0 + row) * DIMV + k0 + q * 4];
            __nv_bfloat162 bh01 = __floats2bfloat162_rn(b.x, b.y);
            __nv_bfloat162 bh23 = __floats2bfloat162_rn(b.z, b.w);
            __nv_bfloat162 bl01 = __floats2bfloat162_rn(b.x - __bfloat162float(bh01.x),
                                                        b.y - __bfloat162float(bh01.y));
            __nv_bfloat162 bl23 = __floats2bfloat162_rn(b.z - __bfloat162float(bh23.x),
                                                        b.w - __bfloat162float(bh23.y));
            asm volatile("st.shared.v2.u32 [%0], {%1,%2};" ::
                "r"(uBh + so), "r"(*(uint32_t*)&bh01), "r"(*(uint32_t*)&bh23));
            asm volatile("st.shared.v2.u32 [%0], {%1,%2};" ::
                "r"(uBl + so), "r"(*(uint32_t*)&bl01), "r"(*(uint32_t*)&bl23));
        }
        __syncthreads();

#pragma unroll
        for (int ks = 0; ks < 4; ks++) {
            const int kk = ks * 16;
            uint32_t bfh[2][4], bfl[2][4];
#pragma unroll
            for (int bi = 0; bi < 2; bi++) {
                uint32_t boff = (uint32_t)((wn * 32 + bi * 16 + b_lrow) * SPK
                                           + kk + b_lkof) * 2;
                ldm_x4(bfh[bi], uBh + boff);
                ldm_x4(bfl[bi], uBl + boff);
            }
#pragma unroll
            for (int mi = 0; mi < 4; mi++) {
                uint32_t af_h[4], af_l[4];
                uint32_t aoff = (uint32_t)((wm * 64 + mi * 16 + a_lrow) * SPK
                                           + kk + a_lkof) * 2;
                ldm_x4(af_h, uAh + aoff);
                ldm_x4(af_l, uAl + aoff);
#pragma unroll
                for (int ni = 0; ni < 4; ni++) {
                    const uint32_t* bh = &bfh[ni >> 1][(ni & 1) * 2];
                    const uint32_t* bl = &bfl[ni >> 1][(ni & 1) * 2];
                    mma_bf16(acc[mi][ni], af_h, bh);
                    mma_bf16(acc[mi][ni], af_h, bl);
                    mma_bf16(acc[mi][ni], af_l, bh);
                }
            }
        }
        __syncthreads();
    }

    const int r_base = wm * 64 + (lane >> 2);
    const int c_base = wn * 32 + (lane & 3) * 2;
#pragma unroll
    for (int mi = 0; mi < 4; mi++) {
#pragma unroll
        for (int ni = 0; ni < 4; ni++) {
            int gcol = n0 + c_base + ni * 8;
#pragma unroll
            for (int half = 0; half < 2; half++) {
                int grow = m0 + r_base + mi * 16 + half * 8;
                float v0 = acc[mi][ni][half * 2 + 0];
                float v1 = acc[mi][ni][half * 2 + 1];
                int qkv = gcol >> 10;
                int hh  = (gcol >> 6) & 15;
                int dd  = gcol & 63;
                int b   = grow >> 10;
                int sp  = grow & 1023;
                size_t off = (((size_t)(b * HEADS + hh) * SEQ) + sp) * HD + dd;
                if (qkv == 2) {
                    /* v -> fp16 hi/lo */
                    __half h0 = __float2half_rn(v0);
                    __half h1 = __float2half_rn(v1);
                    __half l0 = __float2half_rn(v0 - __half2float(h0));
                    __half l1 = __float2half_rn(v1 - __half2float(h1));
                    *(__half2*)&g_vh[off] = __halves2half2(h0, h1);
                    *(__half2*)&g_vl[off] = __halves2half2(l0, l1);
                } else {
                    if (qkv == 0) { v0 *= SCALEF; v1 *= SCALEF; }
                    __nv_bfloat16 h0 = __float2bfloat16_rn(v0);
                    __nv_bfloat16 h1 = __float2bfloat16_rn(v1);
                    __nv_bfloat16 l0 = __float2bfloat16_rn(v0 - __bfloat162float(h0));
                    __nv_bfloat16 l1 = __float2bfloat16_rn(v1 - __bfloat162float(h1));
                    __nv_bfloat16* ph = (qkv == 0) ? g_qh : g_kh;
                    __nv_bfloat16* pl = (qkv == 0) ? g_ql : g_kl;
                    *(__nv_bfloat162*)&ph[off] = __halves2bfloat162(h0, h1);
                    *(__nv_bfloat162*)&pl[off] = __halves2bfloat162(l0, l1);
                }
            }
        }
    }
}

/* ------------------------------------------------------------------ */
/* Proj GEMM: A = g_o fp16 single plane; W fp16 hi/lo inline.          */
/* 2 MMA passes (exact in A). BK=64, 2 CTA/SM.                         */
/* ------------------------------------------------------------------ */
#define PJ_SMEM (3*PL_E*2)

__global__ void __launch_bounds__(256, 2) gemm_proj(
    const float* __restrict__ Bw, const float* __restrict__ bias,
    float* __restrict__ out)
{
    extern __shared__ __nv_bfloat16 smg[];
    const uint32_t s0 = smem_u32(smg);
    const uint32_t uAo = s0;
    const uint32_t uWh = s0 + PL_E * 2;
    const uint32_t uWl = s0 + 2 * PL_E * 2;

    const int tid  = threadIdx.x;
    const int lane = tid & 31;
    const int wid  = tid >> 5;
    const int wm   = wid >> 2;
    const int wn   = wid & 3;
    const int m0   = blockIdx.y * 128;
    const int n0   = blockIdx.x * 128;

    const int a_lrow = (lane & 7) + ((lane >> 3) & 1) * 8;
    const int a_lkof = (lane >> 4) * 8;
    const int b_lrow = (lane & 7) + (lane >> 4) * 8;
    const int b_lkof = ((lane >> 3) & 1) * 8;

    float acc[4][4][4];
#pragma unroll
    for (int i = 0; i < 4; i++)
#pragma unroll
        for (int j = 0; j < 4; j++)
#pragma unroll
            for (int r = 0; r < 4; r++) acc[i][j][r] = 0.f;

    for (int k0 = 0; k0 < DIMV; k0 += 64) {
        /* A: fp16 single plane, 128x64 = 1024 x16B chunks */
#pragma unroll
        for (int j = 0; j < 4; j++) {
            int v   = tid + j * 256;
            int row = v >> 3;
            int c8  = (v & 7) * 8;
            uint32_t so = (uint32_t)(row * SPK + c8) * 2;
            size_t go = (size_t)(m0 + row) * DIMV + k0 + c8;
            uint4 a = *(const uint4*)&g_o[go];
            asm volatile("st.shared.v4.b32 [%0], {%1,%2,%3,%4};" ::
                "r"(uAo + so), "r"(a.x), "r"(a.y), "r"(a.z), "r"(a.w));
        }
        /* W: fp32 load + fp16 hi/lo split, 128x64 */
#pragma unroll
        for (int j = 0; j < 8; j++) {
            int v   = tid + j * 256;
            int row = v >> 4;
            int q   = v & 15;
            uint32_t so = (uint32_t)(row * SPK + q * 4) * 2;
            float4 b = *(const float4*)&Bw[(size_t)(n0 + row) * DIMV + k0 + q * 4];
            __half2 h01 = __floats2half2_rn(b.x, b.y);
            __half2 h23 = __floats2half2_rn(b.z, b.w);
            float2 f01 = __half22float2(h01);
            float2 f23 = __half22float2(h23);
            __half2 l01 = __floats2half2_rn(b.x - f01.x, b.y - f01.y);
            __half2 l23 = __floats2half2_rn(b.z - f23.x, b.w - f23.y);
            asm volatile("st.shared.v2.u32 [%0], {%1,%2};" ::
                "r"(uWh + so), "r"(*(uint32_t*)&h01), "r"(*(uint32_t*)&h23));
            asm volatile("st.shared.v2.u32 [%0], {%1,%2};" ::
                "r"(uWl + so), "r"(*(uint32_t*)&l01), "r"(*(uint32_t*)&l23));
        }
        __syncthreads();

#pragma unroll
        for (int ks = 0; ks < 4; ks++) {
            const int kk = ks * 16;
            uint32_t bfh[2][4], bfl[2][4];
#pragma unroll
            for (int bi = 0; bi < 2; bi++) {
                uint32_t boff = (uint32_t)((wn * 32 + bi * 16 + b_lrow) * SPK
                                           + kk + b_lkof) * 2;
                ldm_x4(bfh[bi], uWh + boff);
                ldm_x4(bfl[bi], uWl + boff);
            }
#pragma unroll
            for (int mi = 0; mi < 4; mi++) {
                uint32_t af[4];
                uint32_t aoff = (uint32_t)((wm * 64 + mi * 16 + a_lrow) * SPK
                                           + kk + a_lkof) * 2;
                ldm_x4(af, uAo + aoff);
#pragma unroll
                for (int ni = 0; ni < 4; ni++) {
                    mma_fp16(acc[mi][ni], af, &bfh[ni >> 1][(ni & 1) * 2]);
                    mma_fp16(acc[mi][ni], af, &bfl[ni >> 1][(ni & 1) * 2]);
                }
            }
        }
        __syncthreads();
    }

    const int r_base = wm * 64 + (lane >> 2);
    const int c_base = wn * 32 + (lane & 3) * 2;
#pragma unroll
    for (int mi = 0; mi < 4; mi++) {
#pragma unroll
        for (int ni = 0; ni < 4; ni++) {
            int gcol = n0 + c_base + ni * 8;
#pragma unroll
            for (int half = 0; half < 2; half++) {
                int grow = m0 + r_base + mi * 16 + half * 8;
                float2 bb = *(const float2*)&bias[gcol];
                *(float2*)&out[(size_t)grow * DIMV + gcol] =
                    make_float2(acc[mi][ni][half * 2 + 0] + bb.x,
                                acc[mi][ni][half * 2 + 1] + bb.y);
            }
        }
    }
}

/* ------------------------------------------------------------------ */
/* Attention: S = bf16 3-pass (proven); PV = fp16 2-pass exact in P.   */
/* Epilogue writes g_o fp16 single plane.                              */
/* ------------------------------------------------------------------ */
#define QP 72

__global__ void __launch_bounds__(256) attn_mma()
{
    extern __shared__ __nv_bfloat16 smb[];
    __nv_bfloat16* Qh = smb;
    __nv_bfloat16* Ql = Qh + 128 * QP;
    __nv_bfloat16* Kh = Ql + 128 * QP;
    __nv_bfloat16* Kl = Kh + 64 * QP;
    __half* Vh = (__half*)(Kl + 64 * QP);
    __half* Vl = Vh + 64 * QP;

    const uint32_t uQh = smem_u32(Qh), uQl = smem_u32(Ql);
    const uint32_t uKh = smem_u32(Kh), uKl = smem_u32(Kl);
    const uint32_t uVh = smem_u32(Vh), uVl = smem_u32(Vl);

    const int tid  = threadIdx.x;
    const int lane = tid & 31;
    const int wid  = tid >> 5;
    const int bh   = blockIdx.y;
    const int m0   = blockIdx.x * 128;

    const size_t pbase = (size_t)bh * SEQ * HD;
    const __nv_bfloat16* pqh = g_qh + pbase;
    const __nv_bfloat16* pql = g_ql + pbase;
    const __nv_bfloat16* pkh = g_kh + pbase;
    const __nv_bfloat16* pkl = g_kl + pbase;
    const __half* pvh = g_vh + pbase;
    const __half* pvl = g_vl + pbase;

#pragma unroll
    for (int t = 0; t < 8; t++) {
        int idx = t * 256 + tid;
        int row = idx >> 4;
        int g   = idx & 15;
        size_t go = (size_t)(m0 + row) * HD + g * 4;
        *(uint2*)&Qh[row * QP + g * 4] = *(const uint2*)&pqh[go];
        *(uint2*)&Ql[row * QP + g * 4] = *(const uint2*)&pql[go];
    }

    float o[8][4];
#pragma unroll
    for (int n = 0; n < 8; n++)
#pragma unroll
        for (int r = 0; r < 4; r++) o[n][r] = 0.f;
    float mrow[2] = {-1e30f, -1e30f};
    float lrow[2] = {0.f, 0.f};

    const int a_row = wid * 16 + (lane & 15);
    const int a_kof = (lane >> 4) * 8;
    const int b_row = (lane & 7) + (lane >> 4) * 8;
    const int b_kof = ((lane >> 3) & 1) * 8;
    const int v_key = ((lane >> 3) & 1) * 8 + (lane & 7);
    const int v_col = (lane >> 4) * 8;

    for (int c = 0; c < 16; c++) {
        const int key0 = c * 64;
        __syncthreads();
#pragma unroll
        for (int t = 0; t < 4; t++) {
            int idx = t * 256 + tid;
            int row = idx >> 4;
            int g   = idx & 15;
            size_t go = (size_t)(key0 + row) * HD + g * 4;
            uint32_t so = row * QP + g * 4;
            *(uint2*)&Kh[so] = *(const uint2*)&pkh[go];
            *(uint2*)&Kl[so] = *(const uint2*)&pkl[go];
            *(uint2*)&Vh[so] = *(const uint2*)&pvh[go];
            *(uint2*)&Vl[so] = *(const uint2*)&pvl[go];
        }
        __syncthreads();

        float s[8][4];
#pragma unroll
        for (int n = 0; n < 8; n++)
#pragma unroll
            for (int r = 0; r < 4; r++) s[n][r] = 0.f;

#pragma unroll
        for (int kk = 0; kk < 4; kk++) {
            uint32_t qhf[4], qlf[4];
            uint32_t aoff = (uint32_t)(a_row * QP + kk * 16 + a_kof) * 2;
            ldm_x4(qhf, uQh + aoff);
            ldm_x4(qlf, uQl + aoff);

            uint32_t kbh[4][4], kbl[4][4];
#pragma unroll
            for (int bi = 0; bi < 4; bi++) {
                uint32_t boff = (uint32_t)((bi * 16 + b_row) * QP + kk * 16 + b_kof) * 2;
                ldm_x4(kbh[bi], uKh + boff);
                ldm_x4(kbl[bi], uKl + boff);
            }
#pragma unroll
            for (int ni = 0; ni < 8; ni++)
                mma_bf16(s[ni], qhf, &kbh[ni >> 1][(ni & 1) * 2]);
#pragma unroll
            for (int ni = 0; ni < 8; ni++)
                mma_bf16(s[ni], qhf, &kbl[ni >> 1][(ni & 1) * 2]);
#pragma unroll
            for (int ni = 0; ni < 8; ni++)
                mma_bf16(s[ni], qlf, &kbh[ni >> 1][(ni & 1) * 2]);
        }

        float alpha[2];
#pragma unroll
        for (int r = 0; r < 2; r++) {
            float mx = -1e30f;
#pragma unroll
            for (int ni = 0; ni < 8; ni++)
                mx = fmaxf(mx, fmaxf(s[ni][r * 2], s[ni][r * 2 + 1]));
            mx = fmaxf(mx, __shfl_xor_sync(0xffffffffu, mx, 1));
            mx = fmaxf(mx, __shfl_xor_sync(0xffffffffu, mx, 2));
            float mnew = fmaxf(mrow[r], mx);
            alpha[r] = __expf(mrow[r] - mnew);
            mrow[r] = mnew;
            float ls = 0.f;
#pragma unroll
            for (int ni = 0; ni < 8; ni++) {
                s[ni][r * 2]     = __expf(s[ni][r * 2]     - mnew);
                s[ni][r * 2 + 1] = __expf(s[ni][r * 2 + 1] - mnew);
                ls += s[ni][r * 2] + s[ni][r * 2 + 1];
            }
            ls += __shfl_xor_sync(0xffffffffu, ls, 1);
            ls += __shfl_xor_sync(0xffffffffu, ls, 2);
            lrow[r] = lrow[r] * alpha[r] + ls;
#pragma unroll
            for (int ni = 0; ni < 8; ni++) {
                o[ni][r * 2]     *= alpha[r];
                o[ni][r * 2 + 1] *= alpha[r];
            }
        }

        /* PV: P fp16 single, V fp16 hi/lo -> 2 passes */
#pragma unroll
        for (int kk = 0; kk < 4; kk++) {
            uint32_t pf[4];
#pragma unroll
            for (int q = 0; q < 4; q++) {
                float f0 = (q & 2) ? s[2 * kk + 1][(q & 1) * 2]     : s[2 * kk][(q & 1) * 2];
                float f1 = (q & 2) ? s[2 * kk + 1][(q & 1) * 2 + 1] : s[2 * kk][(q & 1) * 2 + 1];
                __half2 p2 = __floats2half2_rn(f0, f1);
                pf[q] = *(uint32_t*)&p2;
            }
            uint32_t vbh[4][4], vbl[4][4];
#pragma unroll
            for (int np = 0; np < 4; np++) {
                uint32_t voff = (uint32_t)((kk * 16 + v_key) * QP + np * 16 + v_col) * 2;
                ldm_x4_t(vbh[np], uVh + voff);
                ldm_x4_t(vbl[np], uVl + voff);
            }
#pragma unroll
            for (int ni = 0; ni < 8; ni++)
                mma_fp16(o[ni], pf, &vbh[ni >> 1][(ni & 1) * 2]);
#pragma unroll
            for (int ni = 0; ni < 8; ni++)
                mma_fp16(o[ni], pf, &vbl[ni >> 1][(ni & 1) * 2]);
        }
    }

    /* epilogue: normalize, write fp16 single plane [b,n,dim] */
    const int b = bh >> 4;
    const int h = bh & 15;
#pragma unroll
    for (int r = 0; r < 2; r++) {
        float inv = 1.f / lrow[r];
        int row = m0 + wid * 16 + (lane >> 2) + r * 8;
        size_t base = ((size_t)(b * SEQ + row)) * DIMV + h * HD + (lane & 3) * 2;
#pragma unroll
        for (int ni = 0; ni < 8; ni++) {
            *(__half2*)&g_o[base + ni * 8] =
                __floats2half2_rn(o[ni][r * 2] * inv, o[ni][r * 2 + 1] * inv);
        }
    }
}

/* ------------------------------------------------------------------ */
extern "C" void kernel_launch(void* const* d_in, const int* in_sizes, int n_in,
                              void* d_out, int out_size)
{
    const float* x = nullptr;
    const float* Wqkv = nullptr;
    const float* Wproj = nullptr;
    const float* bproj = nullptr;
    for (int i = 0; i < n_in; i++) {
        switch (in_sizes[i]) {
            case 8388608: x     = (const float*)d_in[i]; break;
            case 3145728: Wqkv  = (const float*)d_in[i]; break;
            case 1048576: Wproj = (const float*)d_in[i]; break;
            case 1024:    bproj = (const float*)d_in[i]; break;
            default: break;
        }
    }
    float* out = (float*)d_out;

    /* QKV GEMM (BK=64, 2 CTA/SM, bf16 3-pass) */
    {
        cudaFuncSetAttribute(gemm_qkv, cudaFuncAttributeMaxDynamicSharedMemorySize,
                             GS_B);
        dim3 grid(3 * DIMV / 128, MTOT / 128);
        gemm_qkv<<<grid, 256, GS_B>>>(x, Wqkv);
    }

    /* attention: S bf16 3-pass, PV fp16 2-pass -> g_o fp16 */
    {
        size_t smem = (size_t)(2 * 128 + 4 * 64) * QP * 2;   /* 73728 */
        cudaFuncSetAttribute(attn_mma, cudaFuncAttributeMaxDynamicSharedMemorySize,
                             (int)smem);
        dim3 grid(SEQ / 128, BATCH * HEADS);
        attn_mma<<<grid, 256, smem>>>();
    }

    /* projection GEMM (fp16 2-pass) + bias */
    {
        cudaFuncSetAttribute(gemm_proj, cudaFuncAttributeMaxDynamicSharedMemorySize,
                             PJ_SMEM);
        dim3 grid(DIMV / 128, MTOT / 128);
        gemm_proj<<<grid, 256, PJ_SMEM>>>(Wproj, bproj, out);
    }
    (void)out_size; (void)n_in;
}

// round 16
// speedup vs baseline: 1.3338x; 1.1793x over previous
#include <cuda_runtime.h>
#include <cuda_fp16.h>
#include <math.h>
#include <stdint.h>

#define DIMV   1024
#define HEADS  16
#define HD     64
#define BATCH  8
#define SEQ    1024
#define MTOT   (BATCH*SEQ)
#define SCALEF 0.125f

/* ------------------------------------------------------------------ */
/* scratch planes: q fp16 single; k,v fp16 hi/lo; o fp16 single        */
/* ------------------------------------------------------------------ */
#define PLANE (BATCH*HEADS*SEQ*HD)
__device__ __half g_q [PLANE];
__device__ __half g_kh[PLANE], g_kl[PLANE];
__device__ __half g_vh[PLANE], g_vl[PLANE];
__device__ __half g_o [(size_t)MTOT*DIMV];

__device__ __forceinline__ uint32_t smem_u32(const void* p) {
    uint32_t a;
    asm("{ .reg .u64 t; cvta.to.shared.u64 t, %1; cvt.u32.u64 %0, t; }"
        : "=r"(a) : "l"(p));
    return a;
}
__device__ __forceinline__ void ldm_x4(uint32_t* r, uint32_t addr) {
    asm volatile("ldmatrix.sync.aligned.m8n8.x4.shared.b16 {%0,%1,%2,%3}, [%4];"
                 : "=r"(r[0]), "=r"(r[1]), "=r"(r[2]), "=r"(r[3]) : "r"(addr));
}
__device__ __forceinline__ void ldm_x4_t(uint32_t* r, uint32_t addr) {
    asm volatile("ldmatrix.sync.aligned.m8n8.x4.trans.shared.b16 {%0,%1,%2,%3}, [%4];"
                 : "=r"(r[0]), "=r"(r[1]), "=r"(r[2]), "=r"(r[3]) : "r"(addr));
}
__device__ __forceinline__ void mma_fp16(float* c, const uint32_t* a, const uint32_t* b) {
    asm volatile("mma.sync.aligned.m16n8k16.row.col.f32.f16.f16.f32 "
                 "{%0,%1,%2,%3}, {%4,%5,%6,%7}, {%8,%9}, {%0,%1,%2,%3};"
                 : "+f"(c[0]), "+f"(c[1]), "+f"(c[2]), "+f"(c[3])
                 : "r"(a[0]), "r"(a[1]), "r"(a[2]), "r"(a[3]), "r"(b[0]), "r"(b[1]));
}

#define SPK   72
#define PL_E  (128*SPK)

/* ------------------------------------------------------------------ */
/* QKV GEMM: x fp16 single + W fp16 hi/lo, 2 MMA passes.               */
/* BK=64, 128x128, 8 warps 2x4, 2 CTA/SM.                              */
/* Epilogue: q -> fp16 single (scaled); k,v -> fp16 hi/lo.             */
/* ------------------------------------------------------------------ */
#define QKV_SMEM (3*PL_E*2)

__global__ void __launch_bounds__(256, 2) gemm_qkv(
    const float* __restrict__ Ap, const float* __restrict__ Bw)
{
    extern __shared__ __half smg[];
    const uint32_t s0 = smem_u32(smg);
    const uint32_t uAf = s0;
    const uint32_t uWh = s0 + PL_E * 2;
    const uint32_t uWl = s0 + 2 * PL_E * 2;

    const int tid  = threadIdx.x;
    const int lane = tid & 31;
    const int wid  = tid >> 5;
    const int wm   = wid >> 2;
    const int wn   = wid & 3;
    const int m0   = blockIdx.y * 128;
    const int n0   = blockIdx.x * 128;

    const int a_lrow = (lane & 7) + ((lane >> 3) & 1) * 8;
    const int a_lkof = (lane >> 4) * 8;
    const int b_lrow = (lane & 7) + (lane >> 4) * 8;
    const int b_lkof = ((lane >> 3) & 1) * 8;

    float acc[4][4][4];
#pragma unroll
    for (int i = 0; i < 4; i++)
#pragma unroll
        for (int j = 0; j < 4; j++)
#pragma unroll
            for (int r = 0; r < 4; r++) acc[i][j][r] = 0.f;

    for (int k0 = 0; k0 < DIMV; k0 += 64) {
        /* x: 128x64 fp32 -> fp16 single */
#pragma unroll
        for (int j = 0; j < 8; j++) {
            int v   = tid + j * 256;
            int row = v >> 4;
            int q   = v & 15;
            uint32_t so = (uint32_t)(row * SPK + q * 4) * 2;
            float4 a = *(const float4*)&Ap[(size_t)(m0 + row) * DIMV + k0 + q * 4];
            __half2 a01 = __floats2half2_rn(a.x, a.y);
            __half2 a23 = __floats2half2_rn(a.z, a.w);
            asm volatile("st.shared.v2.u32 [%0], {%1,%2};" ::
                "r"(uAf + so), "r"(*(uint32_t*)&a01), "r"(*(uint32_t*)&a23));

            float4 b = *(const float4*)&Bw[(size_t)(n0 + row) * DIMV + k0 + q * 4];
            __half2 h01 = __floats2half2_rn(b.x, b.y);
            __half2 h23 = __floats2half2_rn(b.z, b.w);
            float2 f01 = __half22float2(h01);
            float2 f23 = __half22float2(h23);
            __half2 l01 = __floats2half2_rn(b.x - f01.x, b.y - f01.y);
            __half2 l23 = __floats2half2_rn(b.z - f23.x, b.w - f23.y);
            asm volatile("st.shared.v2.u32 [%0], {%1,%2};" ::
                "r"(uWh + so), "r"(*(uint32_t*)&h01), "r"(*(uint32_t*)&h23));
            asm volatile("st.shared.v2.u32 [%0], {%1,%2};" ::
                "r"(uWl + so), "r"(*(uint32_t*)&l01), "r"(*(uint32_t*)&l23));
        }
        __syncthreads();

#pragma unroll
        for (int ks = 0; ks < 4; ks++) {
            const int kk = ks * 16;
            uint32_t bfh[2][4], bfl[2][4];
#pragma unroll
            for (int bi = 0; bi < 2; bi++) {
                uint32_t boff = (uint32_t)((wn * 32 + bi * 16 + b_lrow) * SPK
                                           + kk + b_lkof) * 2;
                ldm_x4(bfh[bi], uWh + boff);
                ldm_x4(bfl[bi], uWl + boff);
            }
#pragma unroll
            for (int mi = 0; mi < 4; mi++) {
                uint32_t af[4];
                uint32_t aoff = (uint32_t)((wm * 64 + mi * 16 + a_lrow) * SPK
                                           + kk + a_lkof) * 2;
                ldm_x4(af, uAf + aoff);
#pragma unroll
                for (int ni = 0; ni < 4; ni++) {
                    mma_fp16(acc[mi][ni], af, &bfh[ni >> 1][(ni & 1) * 2]);
                    mma_fp16(acc[mi][ni], af, &bfl[ni >> 1][(ni & 1) * 2]);
                }
            }
        }
        __syncthreads();
    }

    const int r_base = wm * 64 + (lane >> 2);
    const int c_base = wn * 32 + (lane & 3) * 2;
#pragma unroll
    for (int mi = 0; mi < 4; mi++) {
#pragma unroll
        for (int ni = 0; ni < 4; ni++) {
            int gcol = n0 + c_base + ni * 8;
#pragma unroll
            for (int half = 0; half < 2; half++) {
                int grow = m0 + r_base + mi * 16 + half * 8;
                float v0 = acc[mi][ni][half * 2 + 0];
                float v1 = acc[mi][ni][half * 2 + 1];
                int qkv = gcol >> 10;
                int hh  = (gcol >> 6) & 15;
                int dd  = gcol & 63;
                int b   = grow >> 10;
                int sp  = grow & 1023;
                size_t off = (((size_t)(b * HEADS + hh) * SEQ) + sp) * HD + dd;
                if (qkv == 0) {
                    *(__half2*)&g_q[off] =
                        __floats2half2_rn(v0 * SCALEF, v1 * SCALEF);
                } else {
                    __half h0 = __float2half_rn(v0);
                    __half h1 = __float2half_rn(v1);
                    __half l0 = __float2half_rn(v0 - __half2float(h0));
                    __half l1 = __float2half_rn(v1 - __half2float(h1));
                    __half* ph = (qkv == 1) ? g_kh : g_vh;
                    __half* pl = (qkv == 1) ? g_kl : g_vl;
                    *(__half2*)&ph[off] = __halves2half2(h0, h1);
                    *(__half2*)&pl[off] = __halves2half2(l0, l1);
                }
            }
        }
    }
}

/* ------------------------------------------------------------------ */
/* Proj GEMM (round-15 proven): A = g_o fp16 single; W fp16 hi/lo.     */
/* ------------------------------------------------------------------ */
#define PJ_SMEM (3*PL_E*2)

__global__ void __launch_bounds__(256, 2) gemm_proj(
    const float* __restrict__ Bw, const float* __restrict__ bias,
    float* __restrict__ out)
{
    extern __shared__ __half smg[];
    const uint32_t s0 = smem_u32(smg);
    const uint32_t uAo = s0;
    const uint32_t uWh = s0 + PL_E * 2;
    const uint32_t uWl = s0 + 2 * PL_E * 2;

    const int tid  = threadIdx.x;
    const int lane = tid & 31;
    const int wid  = tid >> 5;
    const int wm   = wid >> 2;
    const int wn   = wid & 3;
    const int m0   = blockIdx.y * 128;
    const int n0   = blockIdx.x * 128;

    const int a_lrow = (lane & 7) + ((lane >> 3) & 1) * 8;
    const int a_lkof = (lane >> 4) * 8;
    const int b_lrow = (lane & 7) + (lane >> 4) * 8;
    const int b_lkof = ((lane >> 3) & 1) * 8;

    float acc[4][4][4];
#pragma unroll
    for (int i = 0; i < 4; i++)
#pragma unroll
        for (int j = 0; j < 4; j++)
#pragma unroll
            for (int r = 0; r < 4; r++) acc[i][j][r] = 0.f;

    for (int k0 = 0; k0 < DIMV; k0 += 64) {
#pragma unroll
        for (int j = 0; j < 4; j++) {
            int v   = tid + j * 256;
            int row = v >> 3;
            int c8  = (v & 7) * 8;
            uint32_t so = (uint32_t)(row * SPK + c8) * 2;
            size_t go = (size_t)(m0 + row) * DIMV + k0 + c8;
            uint4 a = *(const uint4*)&g_o[go];
            asm volatile("st.shared.v4.b32 [%0], {%1,%2,%3,%4};" ::
                "r"(uAo + so), "r"(a.x), "r"(a.y), "r"(a.z), "r"(a.w));
        }
#pragma unroll
        for (int j = 0; j < 8; j++) {
            int v   = tid + j * 256;
            int row = v >> 4;
            int q   = v & 15;
            uint32_t so = (uint32_t)(row * SPK + q * 4) * 2;
            float4 b = *(const float4*)&Bw[(size_t)(n0 + row) * DIMV + k0 + q * 4];
            __half2 h01 = __floats2half2_rn(b.x, b.y);
            __half2 h23 = __floats2half2_rn(b.z, b.w);
            float2 f01 = __half22float2(h01);
            float2 f23 = __half22float2(h23);
            __half2 l01 = __floats2half2_rn(b.x - f01.x, b.y - f01.y);
            __half2 l23 = __floats2half2_rn(b.z - f23.x, b.w - f23.y);
            asm volatile("st.shared.v2.u32 [%0], {%1,%2};" ::
                "r"(uWh + so), "r"(*(uint32_t*)&h01), "r"(*(uint32_t*)&h23));
            asm volatile("st.shared.v2.u32 [%0], {%1,%2};" ::
                "r"(uWl + so), "r"(*(uint32_t*)&l01), "r"(*(uint32_t*)&l23));
        }
        __syncthreads();

#pragma unroll
        for (int ks = 0; ks < 4; ks++) {
            const int kk = ks * 16;
            uint32_t bfh[2][4], bfl[2][4];
#pragma unroll
            for (int bi = 0; bi < 2; bi++) {
                uint32_t boff = (uint32_t)((wn * 32 + bi * 16 + b_lrow) * SPK
                                           + kk + b_lkof) * 2;
                ldm_x4(bfh[bi], uWh + boff);
                ldm_x4(bfl[bi], uWl + boff);
            }
#pragma unroll
            for (int mi = 0; mi < 4; mi++) {
                uint32_t af[4];
                uint32_t aoff = (uint32_t)((wm * 64 + mi * 16 + a_lrow) * SPK
                                           + kk + a_lkof) * 2;
                ldm_x4(af, uAo + aoff);
#pragma unroll
                for (int ni = 0; ni < 4; ni++) {
                    mma_fp16(acc[mi][ni], af, &bfh[ni >> 1][(ni & 1) * 2]);
                    mma_fp16(acc[mi][ni], af, &bfl[ni >> 1][(ni & 1) * 2]);
                }
            }
        }
        __syncthreads();
    }

    const int r_base = wm * 64 + (lane >> 2);
    const int c_base = wn * 32 + (lane & 3) * 2;
#pragma unroll
    for (int mi = 0; mi < 4; mi++) {
#pragma unroll
        for (int ni = 0; ni < 4; ni++) {
            int gcol = n0 + c_base + ni * 8;
#pragma unroll
            for (int half = 0; half < 2; half++) {
                int grow = m0 + r_base + mi * 16 + half * 8;
                float2 bb = *(const float2*)&bias[gcol];
                *(float2*)&out[(size_t)grow * DIMV + gcol] =
                    make_float2(acc[mi][ni][half * 2 + 0] + bb.x,
                                acc[mi][ni][half * 2 + 1] + bb.y);
            }
        }
    }
}

/* ------------------------------------------------------------------ */
/* Attention: S = Qf*(Kh+Kl) 2-pass; PV = Pf*(Vh+Vl) 2-pass.           */
/* Q fp16 single, K/V fp16 hi/lo. Epilogue -> g_o fp16 single.         */
/* ------------------------------------------------------------------ */
#define QP 72

__global__ void __launch_bounds__(256) attn_mma()
{
    extern __shared__ __half smb[];
    __half* Qf = smb;
    __half* Kh = Qf + 128 * QP;
    __half* Kl = Kh + 64 * QP;
    __half* Vh = Kl + 64 * QP;
    __half* Vl = Vh + 64 * QP;

    const uint32_t uQf = smem_u32(Qf);
    const uint32_t uKh = smem_u32(Kh), uKl = smem_u32(Kl);
    const uint32_t uVh = smem_u32(Vh), uVl = smem_u32(Vl);

    const int tid  = threadIdx.x;
    const int lane = tid & 31;
    const int wid  = tid >> 5;
    const int bh   = blockIdx.y;
    const int m0   = blockIdx.x * 128;

    const size_t pbase = (size_t)bh * SEQ * HD;
    const __half* pq  = g_q  + pbase;
    const __half* pkh = g_kh + pbase;
    const __half* pkl = g_kl + pbase;
    const __half* pvh = g_vh + pbase;
    const __half* pvl = g_vl + pbase;

    /* load Q tile (single plane): 128x64 = 2048 uint2 -> 4/thread */
#pragma unroll
    for (int t = 0; t < 4; t++) {
        int idx = t * 256 + tid;          /* 0..1023 */
        int row = idx >> 3;               /* 0..127  */
        int g   = (idx & 7) * 8;          /* col     */
        size_t go = (size_t)(m0 + row) * HD + g;
        uint4 v = *(const uint4*)&pq[go];
        asm volatile("st.shared.v4.b32 [%0], {%1,%2,%3,%4};" ::
            "r"(uQf + (uint32_t)(row * QP + g) * 2), "r"(v.x), "r"(v.y), "r"(v.z), "r"(v.w));
    }

    float o[8][4];
#pragma unroll
    for (int n = 0; n < 8; n++)
#pragma unroll
        for (int r = 0; r < 4; r++) o[n][r] = 0.f;
    float mrow[2] = {-1e30f, -1e30f};
    float lrow[2] = {0.f, 0.f};

    const int a_row = wid * 16 + (lane & 15);
    const int a_kof = (lane >> 4) * 8;
    const int b_row = (lane & 7) + (lane >> 4) * 8;
    const int b_kof = ((lane >> 3) & 1) * 8;
    const int v_key = ((lane >> 3) & 1) * 8 + (lane & 7);
    const int v_col = (lane >> 4) * 8;

    for (int c = 0; c < 16; c++) {
        const int key0 = c * 64;
        __syncthreads();
#pragma unroll
        for (int t = 0; t < 4; t++) {
            int idx = t * 256 + tid;
            int row = idx >> 4;
            int g   = idx & 15;
            size_t go = (size_t)(key0 + row) * HD + g * 4;
            uint32_t so = row * QP + g * 4;
            *(uint2*)&Kh[so] = *(const uint2*)&pkh[go];
            *(uint2*)&Kl[so] = *(const uint2*)&pkl[go];
            *(uint2*)&Vh[so] = *(const uint2*)&pvh[go];
            *(uint2*)&Vl[so] = *(const uint2*)&pvl[go];
        }
        __syncthreads();

        float s[8][4];
#pragma unroll
        for (int n = 0; n < 8; n++)
#pragma unroll
            for (int r = 0; r < 4; r++) s[n][r] = 0.f;

#pragma unroll
        for (int kk = 0; kk < 4; kk++) {
            uint32_t qf[4];
            uint32_t aoff = (uint32_t)(a_row * QP + kk * 16 + a_kof) * 2;
            ldm_x4(qf, uQf + aoff);

            uint32_t kbh[4][4], kbl[4][4];
#pragma unroll
            for (int bi = 0; bi < 4; bi++) {
                uint32_t boff = (uint32_t)((bi * 16 + b_row) * QP + kk * 16 + b_kof) * 2;
                ldm_x4(kbh[bi], uKh + boff);
                ldm_x4(kbl[bi], uKl + boff);
            }
#pragma unroll
            for (int ni = 0; ni < 8; ni++)
                mma_fp16(s[ni], qf, &kbh[ni >> 1][(ni & 1) * 2]);
#pragma unroll
            for (int ni = 0; ni < 8; ni++)
                mma_fp16(s[ni], qf, &kbl[ni >> 1][(ni & 1) * 2]);
        }

        float alpha[2];
#pragma unroll
        for (int r = 0; r < 2; r++) {
            float mx = -1e30f;
#pragma unroll
            for (int ni = 0; ni < 8; ni++)
                mx = fmaxf(mx, fmaxf(s[ni][r * 2], s[ni][r * 2 + 1]));
            mx = fmaxf(mx, __shfl_xor_sync(0xffffffffu, mx, 1));
            mx = fmaxf(mx, __shfl_xor_sync(0xffffffffu, mx, 2));
            float mnew = fmaxf(mrow[r], mx);
            alpha[r] = __expf(mrow[r] - mnew);
            mrow[r] = mnew;
            float ls = 0.f;
#pragma unroll
            for (int ni = 0; ni < 8; ni++) {
                s[ni][r * 2]     = __expf(s[ni][r * 2]     - mnew);
                s[ni][r * 2 + 1] = __expf(s[ni][r * 2 + 1] - mnew);
                ls += s[ni][r * 2] + s[ni][r * 2 + 1];
            }
            ls += __shfl_xor_sync(0xffffffffu, ls, 1);
            ls += __shfl_xor_sync(0xffffffffu, ls, 2);
            lrow[r] = lrow[r] * alpha[r] + ls;
#pragma unroll
            for (int ni = 0; ni < 8; ni++) {
                o[ni][r * 2]     *= alpha[r];
                o[ni][r * 2 + 1] *= alpha[r];
            }
        }

#pragma unroll
        for (int kk = 0; kk < 4; kk++) {
            uint32_t pf[4];
#pragma unroll
            for (int q = 0; q < 4; q++) {
                float f0 = (q & 2) ? s[2 * kk + 1][(q & 1) * 2]     : s[2 * kk][(q & 1) * 2];
                float f1 = (q & 2) ? s[2 * kk + 1][(q & 1) * 2 + 1] : s[2 * kk][(q & 1) * 2 + 1];
                __half2 p2 = __floats2half2_rn(f0, f1);
                pf[q] = *(uint32_t*)&p2;
            }
            uint32_t vbh[4][4], vbl[4][4];
#pragma unroll
            for (int np = 0; np < 4; np++) {
                uint32_t voff = (uint32_t)((kk * 16 + v_key) * QP + np * 16 + v_col) * 2;
                ldm_x4_t(vbh[np], uVh + voff);
                ldm_x4_t(vbl[np], uVl + voff);
            }
#pragma unroll
            for (int ni = 0; ni < 8; ni++)
                mma_fp16(o[ni], pf, &vbh[ni >> 1][(ni & 1) * 2]);
#pragma unroll
            for (int ni = 0; ni < 8; ni++)
                mma_fp16(o[ni], pf, &vbl[ni >> 1][(ni & 1) * 2]);
        }
    }

    const int b = bh >> 4;
    const int h = bh & 15;
#pragma unroll
    for (int r = 0; r < 2; r++) {
        float inv = 1.f / lrow[r];
        int row = m0 + wid * 16 + (lane >> 2) + r * 8;
        size_t base = ((size_t)(b * SEQ + row)) * DIMV + h * HD + (lane & 3) * 2;
#pragma unroll
        for (int ni = 0; ni < 8; ni++) {
            *(__half2*)&g_o[base + ni * 8] =
                __floats2half2_rn(o[ni][r * 2] * inv, o[ni][r * 2 + 1] * inv);
        }
    }
}

/* ------------------------------------------------------------------ */
extern "C" void kernel_launch(void* const* d_in, const int* in_sizes, int n_in,
                              void* d_out, int out_size)
{
    const float* x = nullptr;
    const float* Wqkv = nullptr;
    const float* Wproj = nullptr;
    const float* bproj = nullptr;
    for (int i = 0; i < n_in; i++) {
        switch (in_sizes[i]) {
            case 8388608: x     = (const float*)d_in[i]; break;
            case 3145728: Wqkv  = (const float*)d_in[i]; break;
            case 1048576: Wproj = (const float*)d_in[i]; break;
            case 1024:    bproj = (const float*)d_in[i]; break;
            default: break;
        }
    }
    float* out = (float*)d_out;

    /* QKV GEMM (fp16 2-pass) */
    {
        cudaFuncSetAttribute(gemm_qkv, cudaFuncAttributeMaxDynamicSharedMemorySize,
                             QKV_SMEM);
        dim3 grid(3 * DIMV / 128, MTOT / 128);
        gemm_qkv<<<grid, 256, QKV_SMEM>>>(x, Wqkv);
    }

    /* attention: S 2-pass, PV 2-pass -> g_o fp16 */
    {
        size_t smem = (size_t)(128 + 4 * 64) * QP * 2;   /* 55296 */
        cudaFuncSetAttribute(attn_mma, cudaFuncAttributeMaxDynamicSharedMemorySize,
                             (int)smem);
        dim3 grid(SEQ / 128, BATCH * HEADS);
        attn_mma<<<grid, 256, smem>>>();
    }

    /* projection GEMM (fp16 2-pass) + bias */
    {
        cudaFuncSetAttribute(gemm_proj, cudaFuncAttributeMaxDynamicSharedMemorySize,
                             PJ_SMEM);
        dim3 grid(DIMV / 128, MTOT / 128);
        gemm_proj<<<grid, 256, PJ_SMEM>>>(Wproj, bproj, out);
    }
    (void)out_size; (void)n_in;
}

// round 17
// speedup vs baseline: 1.6553x; 1.2410x over previous
#include <cuda_runtime.h>
#include <cuda_fp16.h>
#include <math.h>
#include <stdint.h>

#define DIMV   1024
#define HEADS  16
#define HD     64
#define BATCH  8
#define SEQ    1024
#define MTOT   (BATCH*SEQ)
#define SCALEF 0.125f

/* ------------------------------------------------------------------ */
/* scratch planes: all single fp16                                     */
/* ------------------------------------------------------------------ */
#define PLANE (BATCH*HEADS*SEQ*HD)
__device__ __half g_q[PLANE], g_k[PLANE], g_v[PLANE];
__device__ __half g_o[(size_t)MTOT*DIMV];

__device__ __forceinline__ uint32_t smem_u32(const void* p) {
    uint32_t a;
    asm("{ .reg .u64 t; cvta.to.shared.u64 t, %1; cvt.u32.u64 %0, t; }"
        : "=r"(a) : "l"(p));
    return a;
}
__device__ __forceinline__ void ldm_x4(uint32_t* r, uint32_t addr) {
    asm volatile("ldmatrix.sync.aligned.m8n8.x4.shared.b16 {%0,%1,%2,%3}, [%4];"
                 : "=r"(r[0]), "=r"(r[1]), "=r"(r[2]), "=r"(r[3]) : "r"(addr));
}
__device__ __forceinline__ void ldm_x4_t(uint32_t* r, uint32_t addr) {
    asm volatile("ldmatrix.sync.aligned.m8n8.x4.trans.shared.b16 {%0,%1,%2,%3}, [%4];"
                 : "=r"(r[0]), "=r"(r[1]), "=r"(r[2]), "=r"(r[3]) : "r"(addr));
}
__device__ __forceinline__ void mma_fp16(float* c, const uint32_t* a, const uint32_t* b) {
    asm volatile("mma.sync.aligned.m16n8k16.row.col.f32.f16.f16.f32 "
                 "{%0,%1,%2,%3}, {%4,%5,%6,%7}, {%8,%9}, {%0,%1,%2,%3};"
                 : "+f"(c[0]), "+f"(c[1]), "+f"(c[2]), "+f"(c[3])
                 : "r"(a[0]), "r"(a[1]), "r"(a[2]), "r"(a[3]), "r"(b[0]), "r"(b[1]));
}

#define SPK   72
#define PL_E  (128*SPK)

/* ------------------------------------------------------------------ */
/* QKV GEMM: x fp16 + W fp16, 1 MMA pass. BK=64, 128x128, 2 CTA/SM.    */
/* Epilogue: q (scaled), k, v -> single fp16 planes.                   */
/* ------------------------------------------------------------------ */
#define QKV_SMEM (2*PL_E*2)

__global__ void __launch_bounds__(256, 2) gemm_qkv(
    const float* __restrict__ Ap, const float* __restrict__ Bw)
{
    extern __shared__ __half smg[];
    const uint32_t s0 = smem_u32(smg);
    const uint32_t uAf = s0;
    const uint32_t uWf = s0 + PL_E * 2;

    const int tid  = threadIdx.x;
    const int lane = tid & 31;
    const int wid  = tid >> 5;
    const int wm   = wid >> 2;
    const int wn   = wid & 3;
    const int m0   = blockIdx.y * 128;
    const int n0   = blockIdx.x * 128;

    const int a_lrow = (lane & 7) + ((lane >> 3) & 1) * 8;
    const int a_lkof = (lane >> 4) * 8;
    const int b_lrow = (lane & 7) + (lane >> 4) * 8;
    const int b_lkof = ((lane >> 3) & 1) * 8;

    float acc[4][4][4];
#pragma unroll
    for (int i = 0; i < 4; i++)
#pragma unroll
        for (int j = 0; j < 4; j++)
#pragma unroll
            for (int r = 0; r < 4; r++) acc[i][j][r] = 0.f;

    for (int k0 = 0; k0 < DIMV; k0 += 64) {
#pragma unroll
        for (int j = 0; j < 8; j++) {
            int v   = tid + j * 256;
            int row = v >> 4;
            int q   = v & 15;
            uint32_t so = (uint32_t)(row * SPK + q * 4) * 2;

            float4 a = *(const float4*)&Ap[(size_t)(m0 + row) * DIMV + k0 + q * 4];
            __half2 a01 = __floats2half2_rn(a.x, a.y);
            __half2 a23 = __floats2half2_rn(a.z, a.w);
            asm volatile("st.shared.v2.u32 [%0], {%1,%2};" ::
                "r"(uAf + so), "r"(*(uint32_t*)&a01), "r"(*(uint32_t*)&a23));

            float4 b = *(const float4*)&Bw[(size_t)(n0 + row) * DIMV + k0 + q * 4];
            __half2 b01 = __floats2half2_rn(b.x, b.y);
            __half2 b23 = __floats2half2_rn(b.z, b.w);
            asm volatile("st.shared.v2.u32 [%0], {%1,%2};" ::
                "r"(uWf + so), "r"(*(uint32_t*)&b01), "r"(*(uint32_t*)&b23));
        }
        __syncthreads();

#pragma unroll
        for (int ks = 0; ks < 4; ks++) {
            const int kk = ks * 16;
            uint32_t bf[2][4];
#pragma unroll
            for (int bi = 0; bi < 2; bi++) {
                uint32_t boff = (uint32_t)((wn * 32 + bi * 16 + b_lrow) * SPK
                                           + kk + b_lkof) * 2;
                ldm_x4(bf[bi], uWf + boff);
            }
#pragma unroll
            for (int mi = 0; mi < 4; mi++) {
                uint32_t af[4];
                uint32_t aoff = (uint32_t)((wm * 64 + mi * 16 + a_lrow) * SPK
                                           + kk + a_lkof) * 2;
                ldm_x4(af, uAf + aoff);
#pragma unroll
                for (int ni = 0; ni < 4; ni++)
                    mma_fp16(acc[mi][ni], af, &bf[ni >> 1][(ni & 1) * 2]);
            }
        }
        __syncthreads();
    }

    const int r_base = wm * 64 + (lane >> 2);
    const int c_base = wn * 32 + (lane & 3) * 2;
#pragma unroll
    for (int mi = 0; mi < 4; mi++) {
#pragma unroll
        for (int ni = 0; ni < 4; ni++) {
            int gcol = n0 + c_base + ni * 8;
#pragma unroll
            for (int half = 0; half < 2; half++) {
                int grow = m0 + r_base + mi * 16 + half * 8;
                float v0 = acc[mi][ni][half * 2 + 0];
                float v1 = acc[mi][ni][half * 2 + 1];
                int qkv = gcol >> 10;
                int hh  = (gcol >> 6) & 15;
                int dd  = gcol & 63;
                int b   = grow >> 10;
                int sp  = grow & 1023;
                size_t off = (((size_t)(b * HEADS + hh) * SEQ) + sp) * HD + dd;
                if (qkv == 0) { v0 *= SCALEF; v1 *= SCALEF; }
                __half* dst = (qkv == 0) ? g_q : (qkv == 1) ? g_k : g_v;
                *(__half2*)&dst[off] = __floats2half2_rn(v0, v1);
            }
        }
    }
}

/* ------------------------------------------------------------------ */
/* Proj GEMM: A = g_o fp16, W fp16, 1 MMA pass. +bias fp32 out.        */
/* ------------------------------------------------------------------ */
#define PJ_SMEM (2*PL_E*2)

__global__ void __launch_bounds__(256, 2) gemm_proj(
    const float* __restrict__ Bw, const float* __restrict__ bias,
    float* __restrict__ out)
{
    extern __shared__ __half smg[];
    const uint32_t s0 = smem_u32(smg);
    const uint32_t uAo = s0;
    const uint32_t uWf = s0 + PL_E * 2;

    const int tid  = threadIdx.x;
    const int lane = tid & 31;
    const int wid  = tid >> 5;
    const int wm   = wid >> 2;
    const int wn   = wid & 3;
    const int m0   = blockIdx.y * 128;
    const int n0   = blockIdx.x * 128;

    const int a_lrow = (lane & 7) + ((lane >> 3) & 1) * 8;
    const int a_lkof = (lane >> 4) * 8;
    const int b_lrow = (lane & 7) + (lane >> 4) * 8;
    const int b_lkof = ((lane >> 3) & 1) * 8;

    float acc[4][4][4];
#pragma unroll
    for (int i = 0; i < 4; i++)
#pragma unroll
        for (int j = 0; j < 4; j++)
#pragma unroll
            for (int r = 0; r < 4; r++) acc[i][j][r] = 0.f;

    for (int k0 = 0; k0 < DIMV; k0 += 64) {
        /* A: direct fp16 copies */
#pragma unroll
        for (int j = 0; j < 4; j++) {
            int v   = tid + j * 256;
            int row = v >> 3;
            int c8  = (v & 7) * 8;
            uint32_t so = (uint32_t)(row * SPK + c8) * 2;
            size_t go = (size_t)(m0 + row) * DIMV + k0 + c8;
            uint4 a = *(const uint4*)&g_o[go];
            asm volatile("st.shared.v4.b32 [%0], {%1,%2,%3,%4};" ::
                "r"(uAo + so), "r"(a.x), "r"(a.y), "r"(a.z), "r"(a.w));
        }
        /* W: fp32 -> fp16 single */
#pragma unroll
        for (int j = 0; j < 8; j++) {
            int v   = tid + j * 256;
            int row = v >> 4;
            int q   = v & 15;
            uint32_t so = (uint32_t)(row * SPK + q * 4) * 2;
            float4 b = *(const float4*)&Bw[(size_t)(n0 + row) * DIMV + k0 + q * 4];
            __half2 b01 = __floats2half2_rn(b.x, b.y);
            __half2 b23 = __floats2half2_rn(b.z, b.w);
            asm volatile("st.shared.v2.u32 [%0], {%1,%2};" ::
                "r"(uWf + so), "r"(*(uint32_t*)&b01), "r"(*(uint32_t*)&b23));
        }
        __syncthreads();

#pragma unroll
        for (int ks = 0; ks < 4; ks++) {
            const int kk = ks * 16;
            uint32_t bf[2][4];
#pragma unroll
            for (int bi = 0; bi < 2; bi++) {
                uint32_t boff = (uint32_t)((wn * 32 + bi * 16 + b_lrow) * SPK
                                           + kk + b_lkof) * 2;
                ldm_x4(bf[bi], uWf + boff);
            }
#pragma unroll
            for (int mi = 0; mi < 4; mi++) {
                uint32_t af[4];
                uint32_t aoff = (uint32_t)((wm * 64 + mi * 16 + a_lrow) * SPK
                                           + kk + a_lkof) * 2;
                ldm_x4(af, uAo + aoff);
#pragma unroll
                for (int ni = 0; ni < 4; ni++)
                    mma_fp16(acc[mi][ni], af, &bf[ni >> 1][(ni & 1) * 2]);
            }
        }
        __syncthreads();
    }

    const int r_base = wm * 64 + (lane >> 2);
    const int c_base = wn * 32 + (lane & 3) * 2;
#pragma unroll
    for (int mi = 0; mi < 4; mi++) {
#pragma unroll
        for (int ni = 0; ni < 4; ni++) {
            int gcol = n0 + c_base + ni * 8;
#pragma unroll
            for (int half = 0; half < 2; half++) {
                int grow = m0 + r_base + mi * 16 + half * 8;
                float2 bb = *(const float2*)&bias[gcol];
                *(float2*)&out[(size_t)grow * DIMV + gcol] =
                    make_float2(acc[mi][ni][half * 2 + 0] + bb.x,
                                acc[mi][ni][half * 2 + 1] + bb.y);
            }
        }
    }
}

/* ------------------------------------------------------------------ */
/* Attention: all single fp16, S 1-pass, PV 1-pass.                    */
/* ------------------------------------------------------------------ */
#define QP 72

__global__ void __launch_bounds__(256) attn_mma()
{
    extern __shared__ __half smb[];
    __half* Qf = smb;
    __half* Kf = Qf + 128 * QP;
    __half* Vf = Kf + 64 * QP;

    const uint32_t uQf = smem_u32(Qf);
    const uint32_t uKf = smem_u32(Kf);
    const uint32_t uVf = smem_u32(Vf);

    const int tid  = threadIdx.x;
    const int lane = tid & 31;
    const int wid  = tid >> 5;
    const int bh   = blockIdx.y;
    const int m0   = blockIdx.x * 128;

    const size_t pbase = (size_t)bh * SEQ * HD;
    const __half* pq = g_q + pbase;
    const __half* pk = g_k + pbase;
    const __half* pv = g_v + pbase;

    /* load Q tile: 128x64 fp16 = 1024 x16B */
#pragma unroll
    for (int t = 0; t < 4; t++) {
        int idx = t * 256 + tid;
        int row = idx >> 3;
        int g   = (idx & 7) * 8;
        size_t go = (size_t)(m0 + row) * HD + g;
        uint4 v = *(const uint4*)&pq[go];
        asm volatile("st.shared.v4.b32 [%0], {%1,%2,%3,%4};" ::
            "r"(uQf + (uint32_t)(row * QP + g) * 2), "r"(v.x), "r"(v.y), "r"(v.z), "r"(v.w));
    }

    float o[8][4];
#pragma unroll
    for (int n = 0; n < 8; n++)
#pragma unroll
        for (int r = 0; r < 4; r++) o[n][r] = 0.f;
    float mrow[2] = {-1e30f, -1e30f};
    float lrow[2] = {0.f, 0.f};

    const int a_row = wid * 16 + (lane & 15);
    const int a_kof = (lane >> 4) * 8;
    const int b_row = (lane & 7) + (lane >> 4) * 8;
    const int b_kof = ((lane >> 3) & 1) * 8;
    const int v_key = ((lane >> 3) & 1) * 8 + (lane & 7);
    const int v_col = (lane >> 4) * 8;

    for (int c = 0; c < 16; c++) {
        const int key0 = c * 64;
        __syncthreads();
        /* K,V tiles: 64x64 each = 512 x16B chunks */
#pragma unroll
        for (int t = 0; t < 2; t++) {
            int idx = t * 256 + tid;
            int row = idx >> 3;
            int g   = (idx & 7) * 8;
            size_t go = (size_t)(key0 + row) * HD + g;
            uint32_t so = (uint32_t)(row * QP + g) * 2;
            uint4 kv = *(const uint4*)&pk[go];
            uint4 vv = *(const uint4*)&pv[go];
            asm volatile("st.shared.v4.b32 [%0], {%1,%2,%3,%4};" ::
                "r"(uKf + so), "r"(kv.x), "r"(kv.y), "r"(kv.z), "r"(kv.w));
            asm volatile("st.shared.v4.b32 [%0], {%1,%2,%3,%4};" ::
                "r"(uVf + so), "r"(vv.x), "r"(vv.y), "r"(vv.z), "r"(vv.w));
        }
        __syncthreads();

        float s[8][4];
#pragma unroll
        for (int n = 0; n < 8; n++)
#pragma unroll
            for (int r = 0; r < 4; r++) s[n][r] = 0.f;

#pragma unroll
        for (int kk = 0; kk < 4; kk++) {
            uint32_t qf[4];
            uint32_t aoff = (uint32_t)(a_row * QP + kk * 16 + a_kof) * 2;
            ldm_x4(qf, uQf + aoff);

            uint32_t kb[4][4];
#pragma unroll
            for (int bi = 0; bi < 4; bi++) {
                uint32_t boff = (uint32_t)((bi * 16 + b_row) * QP + kk * 16 + b_kof) * 2;
                ldm_x4(kb[bi], uKf + boff);
            }
#pragma unroll
            for (int ni = 0; ni < 8; ni++)
                mma_fp16(s[ni], qf, &kb[ni >> 1][(ni & 1) * 2]);
        }

        float alpha[2];
#pragma unroll
        for (int r = 0; r < 2; r++) {
            float mx = -1e30f;
#pragma unroll
            for (int ni = 0; ni < 8; ni++)
                mx = fmaxf(mx, fmaxf(s[ni][r * 2], s[ni][r * 2 + 1]));
            mx = fmaxf(mx, __shfl_xor_sync(0xffffffffu, mx, 1));
            mx = fmaxf(mx, __shfl_xor_sync(0xffffffffu, mx, 2));
            float mnew = fmaxf(mrow[r], mx);
            alpha[r] = __expf(mrow[r] - mnew);
            mrow[r] = mnew;
            float ls = 0.f;
#pragma unroll
            for (int ni = 0; ni < 8; ni++) {
                s[ni][r * 2]     = __expf(s[ni][r * 2]     - mnew);
                s[ni][r * 2 + 1] = __expf(s[ni][r * 2 + 1] - mnew);
                ls += s[ni][r * 2] + s[ni][r * 2 + 1];
            }
            ls += __shfl_xor_sync(0xffffffffu, ls, 1);
            ls += __shfl_xor_sync(0xffffffffu, ls, 2);
            lrow[r] = lrow[r] * alpha[r] + ls;
#pragma unroll
            for (int ni = 0; ni < 8; ni++) {
                o[ni][r * 2]     *= alpha[r];
                o[ni][r * 2 + 1] *= alpha[r];
            }
        }

#pragma unroll
        for (int kk = 0; kk < 4; kk++) {
            uint32_t pf[4];
#pragma unroll
            for (int q = 0; q < 4; q++) {
                float f0 = (q & 2) ? s[2 * kk + 1][(q & 1) * 2]     : s[2 * kk][(q & 1) * 2];
                float f1 = (q & 2) ? s[2 * kk + 1][(q & 1) * 2 + 1] : s[2 * kk][(q & 1) * 2 + 1];
                __half2 p2 = __floats2half2_rn(f0, f1);
                pf[q] = *(uint32_t*)&p2;
            }
            uint32_t vb[4][4];
#pragma unroll
            for (int np = 0; np < 4; np++) {
                uint32_t voff = (uint32_t)((kk * 16 + v_key) * QP + np * 16 + v_col) * 2;
                ldm_x4_t(vb[np], uVf + voff);
            }
#pragma unroll
            for (int ni = 0; ni < 8; ni++)
                mma_fp16(o[ni], pf, &vb[ni >> 1][(ni & 1) * 2]);
        }
    }

    const int b = bh >> 4;
    const int h = bh & 15;
#pragma unroll
    for (int r = 0; r < 2; r++) {
        float inv = 1.f / lrow[r];
        int row = m0 + wid * 16 + (lane >> 2) + r * 8;
        size_t base = ((size_t)(b * SEQ + row)) * DIMV + h * HD + (lane & 3) * 2;
#pragma unroll
        for (int ni = 0; ni < 8; ni++) {
            *(__half2*)&g_o[base + ni * 8] =
                __floats2half2_rn(o[ni][r * 2] * inv, o[ni][r * 2 + 1] * inv);
        }
    }
}

/* ------------------------------------------------------------------ */
extern "C" void kernel_launch(void* const* d_in, const int* in_sizes, int n_in,
                              void* d_out, int out_size)
{
    const float* x = nullptr;
    const float* Wqkv = nullptr;
    const float* Wproj = nullptr;
    const float* bproj = nullptr;
    for (int i = 0; i < n_in; i++) {
        switch (in_sizes[i]) {
            case 8388608: x     = (const float*)d_in[i]; break;
            case 3145728: Wqkv  = (const float*)d_in[i]; break;
            case 1048576: Wproj = (const float*)d_in[i]; break;
            case 1024:    bproj = (const float*)d_in[i]; break;
            default: break;
        }
    }
    float* out = (float*)d_out;

    /* QKV GEMM (fp16 1-pass) */
    {
        cudaFuncSetAttribute(gemm_qkv, cudaFuncAttributeMaxDynamicSharedMemorySize,
                             QKV_SMEM);
        dim3 grid(3 * DIMV / 128, MTOT / 128);
        gemm_qkv<<<grid, 256, QKV_SMEM>>>(x, Wqkv);
    }

    /* attention (fp16 1-pass S and PV) */
    {
        size_t smem = (size_t)(128 + 2 * 64) * QP * 2;   /* 36864 */
        cudaFuncSetAttribute(attn_mma, cudaFuncAttributeMaxDynamicSharedMemorySize,
                             (int)smem);
        dim3 grid(SEQ / 128, BATCH * HEADS);
        attn_mma<<<grid, 256, smem>>>();
    }

    /* projection GEMM (fp16 1-pass) + bias */
    {
        cudaFuncSetAttribute(gemm_proj, cudaFuncAttributeMaxDynamicSharedMemorySize,
                             PJ_SMEM);
        dim3 grid(DIMV / 128, MTOT / 128);
        gemm_proj<<<grid, 256, PJ_SMEM>>>(Wproj, bproj, out);
    }
    (void)out_size; (void)n_in;
}